// round 3
// baseline (speedup 1.0000x reference)
#include <cuda_runtime.h>
#include <math.h>

#define T_STEPS 512
#define BATCH   128
#define HID     512
#define GATES   1536
#define MROWS   (T_STEPS*BATCH)

__device__ float g_xW[(size_t)MROWS * GATES];   // 402 MB scratch
__device__ int          g_cnt   = 0;
__device__ volatile int g_sense = 0;

__device__ __forceinline__ unsigned long long packf2(float lo, float hi) {
    unsigned long long r;
    asm("mov.b64 %0, {%1, %2};" : "=l"(r) : "f"(lo), "f"(hi));
    return r;
}
__device__ __forceinline__ void unpackf2(unsigned long long v, float& lo, float& hi) {
    asm("mov.b64 {%0, %1}, %2;" : "=f"(lo), "=f"(hi) : "l"(v));
}
__device__ __forceinline__ void fma2(unsigned long long& acc,
                                     unsigned long long a, unsigned long long b) {
    asm("fma.rn.f32x2 %0, %1, %2, %0;" : "+l"(acc) : "l"(a), "l"(b));
}
__device__ __forceinline__ float sigm(float x)  { return 1.0f / (1.0f + __expf(-x)); }
__device__ __forceinline__ float tanhx(float x) { return 1.0f - 2.0f / (__expf(2.0f * x) + 1.0f); }

// ============================ Phase 1: xW GEMM =============================
__global__ __launch_bounds__(256, 2)
void xw_gemm(const float* __restrict__ A, const float* __restrict__ B,
             const float* __restrict__ bi)
{
    __shared__ __align__(16) float As[8][132];
    __shared__ __align__(16) float Bs[8][128];
    const int tid = threadIdx.x;
    const int mb = blockIdx.y * 128, nb = blockIdx.x * 128;
    const int arow = tid >> 1, ak = (tid & 1) * 4;
    const int brow = tid >> 5, bcol = (tid & 31) * 4;
    const int ty8 = (tid >> 4) * 8, tx8 = (tid & 15) * 8;

    unsigned long long acc[32];
#pragma unroll
    for (int i = 0; i < 32; i++) acc[i] = 0ull;

    const float* Ap = A + (size_t)(mb + arow) * HID + ak;
    const float* Bp = B + (size_t)brow * GATES + nb + bcol;

    for (int kt = 0; kt < 64; kt++) {
        float4 ra = *(const float4*)(Ap + kt * 8);
        float4 rb = *(const float4*)(Bp + (size_t)kt * 8 * GATES);
        As[ak + 0][arow] = ra.x; As[ak + 1][arow] = ra.y;
        As[ak + 2][arow] = ra.z; As[ak + 3][arow] = ra.w;
        *(float4*)&Bs[brow][bcol] = rb;
        __syncthreads();
#pragma unroll
        for (int kk = 0; kk < 8; kk++) {
            float4 a0 = *(const float4*)&As[kk][ty8];
            float4 a1 = *(const float4*)&As[kk][ty8 + 4];
            ulonglong2 b0 = *(const ulonglong2*)&Bs[kk][tx8];
            ulonglong2 b1 = *(const ulonglong2*)&Bs[kk][tx8 + 4];
            float ar[8] = {a0.x, a0.y, a0.z, a0.w, a1.x, a1.y, a1.z, a1.w};
#pragma unroll
            for (int i = 0; i < 8; i++) {
                unsigned long long av = packf2(ar[i], ar[i]);
                fma2(acc[i*4+0], av, b0.x); fma2(acc[i*4+1], av, b0.y);
                fma2(acc[i*4+2], av, b1.x); fma2(acc[i*4+3], av, b1.y);
            }
        }
        __syncthreads();
    }
    float4 c0 = *(const float4*)&bi[nb + tx8];
    float4 c1 = *(const float4*)&bi[nb + tx8 + 4];
#pragma unroll
    for (int i = 0; i < 8; i++) {
        float4 o0, o1;
        unpackf2(acc[i*4+0], o0.x, o0.y); unpackf2(acc[i*4+1], o0.z, o0.w);
        unpackf2(acc[i*4+2], o1.x, o1.y); unpackf2(acc[i*4+3], o1.z, o1.w);
        o0.x += c0.x; o0.y += c0.y; o0.z += c0.z; o0.w += c0.w;
        o1.x += c1.x; o1.y += c1.y; o1.z += c1.z; o1.w += c1.w;
        size_t off = (size_t)(mb + ty8 + i) * GATES + nb + tx8;
        *(float4*)&g_xW[off] = o0; *(float4*)&g_xW[off + 4] = o1;
    }
}

// ============================ Phase 2: GRU scan ============================
#define HSTR 520
#define WSF  (HID * 48)                      // 24576 floats
#define SCAN_SMEM ((WSF + 32 * HSTR) * 4)    // 164,864 B

__device__ __forceinline__ void gridbar(int nb) {
    __threadfence();
    __syncthreads();
    if (threadIdx.x == 0) {
        int s = g_sense;
        if (atomicAdd(&g_cnt, 1) == nb - 1) {
            g_cnt = 0;
            __threadfence();
            g_sense = s ^ 1;
        } else {
            while (g_sense == s) { }
        }
    }
    __syncthreads();
    __threadfence();
}

__global__ __launch_bounds__(256, 1)
void gru_scan(const unsigned int* __restrict__ resets,
              const float* __restrict__ Wh,
              const float* __restrict__ bhn,
              float* __restrict__ out)
{
    extern __shared__ __align__(16) float sm[];
    float* ws  = sm;            // [512][48]  gate-major: k*48 + g*16 + jl
    float* hsh = sm + WSF;      // [32][HSTR]
    __shared__ unsigned int rfl[32];

    const int bx = blockIdx.x;
    const int rc = bx & 3, jc = bx >> 2;
    const int r0 = rc * 32, j0g = jc * 16;
    const int tid = threadIdx.x;
    const int row = tid >> 3, cu = tid & 7;
    const int jg0 = j0g + 2 * cu;
    const int bglob = r0 + row;

    for (int idx = tid; idx < HID * 48; idx += 256) {
        int k = idx / 48, c = idx - k * 48;
        int g = c >> 4, jl = c & 15;
        ws[idx] = Wh[(size_t)k * GATES + g * HID + j0g + jl];
    }
    const float2 bh = *(const float2*)&bhn[jg0];
    __syncthreads();

    for (int t = 0; t < T_STEPS; t++) {
        const float* xrow = g_xW + (size_t)(t * BATCH + bglob) * GATES;
        const float2 xr = *(const float2*)(xrow + jg0);
        const float2 xz = *(const float2*)(xrow + HID + jg0);
        const float2 xn = *(const float2*)(xrow + 2 * HID + jg0);

        if (tid < 32) rfl[tid] = (t == 0) ? 1u : resets[t * BATCH + r0 + tid];
        __syncthreads();

        if (t == 0) {
            float4 z4 = make_float4(0.f, 0.f, 0.f, 0.f);
#pragma unroll
            for (int i = 0; i < 16; i++) {
                int e4 = tid + i * 256, hr = e4 >> 7;
                *(float4*)&hsh[hr * HSTR + (e4 & 127) * 4] = z4;
            }
        } else {
            const float* hp = out + (size_t)(t - 1) * (BATCH * HID) + (size_t)r0 * HID;
#pragma unroll
            for (int i = 0; i < 16; i++) {
                int e4 = tid + i * 256, hr = e4 >> 7;
                float4 v = *(const float4*)(hp + (size_t)e4 * 4);
                if (rfl[hr]) v = make_float4(0.f, 0.f, 0.f, 0.f);
                *(float4*)&hsh[hr * HSTR + (e4 & 127) * 4] = v;
            }
        }
        __syncthreads();

        unsigned long long ar_ = 0ull, az_ = 0ull, an_ = 0ull;
        const float* hr_ = &hsh[row * HSTR];
        const float* wp  = ws + 2 * cu;
#pragma unroll 4
        for (int k = 0; k < HID; k++) {
            float a = hr_[k];
            unsigned long long av = packf2(a, a);
            const float* w = wp + k * 48;
            fma2(ar_, av, *(const unsigned long long*)(w));
            fma2(az_, av, *(const unsigned long long*)(w + 16));
            fma2(an_, av, *(const unsigned long long*)(w + 32));
        }

        float hr0, hr1, hz0, hz1, hn0, hn1;
        unpackf2(ar_, hr0, hr1); unpackf2(az_, hz0, hz1); unpackf2(an_, hn0, hn1);

        float hp0 = hr_[jg0], hp1 = hr_[jg0 + 1];
        float r0g = sigm(xr.x + hr0), r1g = sigm(xr.y + hr1);
        float z0g = sigm(xz.x + hz0), z1g = sigm(xz.y + hz1);
        float n0g = tanhx(xn.x + r0g * (hn0 + bh.x));
        float n1g = tanhx(xn.y + r1g * (hn1 + bh.y));
        float2 hnew;
        hnew.x = (1.0f - z0g) * n0g + z0g * hp0;
        hnew.y = (1.0f - z1g) * n1g + z1g * hp1;

        *(float2*)(out + (size_t)(t * BATCH + bglob) * HID + jg0) = hnew;

        gridbar(gridDim.x);
    }
}

// ================================ Launch ===================================
extern "C" void kernel_launch(void* const* d_in, const int* in_sizes, int n_in,
                              void* d_out, int out_size)
{
    const float*        ins    = (const float*)d_in[0];
    const unsigned int* resets = (const unsigned int*)d_in[1];
    const float*        Wi     = (const float*)d_in[2];
    const float*        bi     = (const float*)d_in[3];
    const float*        Wh     = (const float*)d_in[4];
    const float*        bhn    = (const float*)d_in[5];
    float*              out    = (float*)d_out;

    dim3 g1(GATES / 128, MROWS / 128);
    xw_gemm<<<g1, 256>>>(ins, Wi, bi);

    cudaFuncSetAttribute(gru_scan, cudaFuncAttributeMaxDynamicSharedMemorySize, SCAN_SMEM);
    gru_scan<<<128, 256, SCAN_SMEM>>>(resets, Wh, bhn, out);
}